// round 7
// baseline (speedup 1.0000x reference)
#include <cuda_runtime.h>

// Ax[b,m,t] = sum_{c=0..7} x[b, m*8+c, t] * W[m,c]
// x: (16, 1024, 2048) f32, W: (128, 8) f32
// out: Ax (4194304 floats) then A_full (128*1024 floats).
// Each thread produces FOUR float4 outputs (t4, t4+128, t4+256, t4+384 of one
// (b,m) channel group), as two 16-load halves. Exact-cover grid = 1056 blocks
// = one full 8-resident wave on 148 SMs.

#define B_ 16
#define M_ 128
#define C_ 8
#define T_ 2048
#define T4_ (T_ / 4)                   // 512 float4 per channel row
#define QTR_ 128                       // quarter of a row in float4
#define AX_ELEMS (B_ * M_ * T_)        // 4194304
#define AX_VEC   (AX_ELEMS / 4)        // 1048576 float4
#define AX_QUADS (AX_VEC / 4)          // 262144
#define AF_ELEMS (M_ * 1024)           // 131072
#define AF_VEC   (AF_ELEMS / 4)        // 32768 float4
#define AF_QUADS (AF_VEC / 4)          // 8192
#define TOTAL_QUADS (AX_QUADS + AF_QUADS)  // 270336

#define NTHREADS 256
#define NBLOCKS (TOTAL_QUADS / NTHREADS)   // 1056, exact; <= 1184 -> one wave

__global__ void __launch_bounds__(NTHREADS)
fused_kernel(const float* __restrict__ x, const float* __restrict__ W,
             float* __restrict__ out)
{
    int qid = blockIdx.x * NTHREADS + threadIdx.x;

    if (qid < AX_QUADS) {
        // ---- Ax path: four float4 outputs of one (b,m) channel group ----
        int t4 = qid & (QTR_ - 1);         // 0..127
        int m  = (qid >> 7) & (M_ - 1);    // 0..127
        int b  = qid >> 14;                // 0..15

        const float4* xb = (const float4*)(x + ((size_t)(b * 1024 + m * C_) * T_)) + t4;
        const float*  w  = W + m * C_;     // uniform within warp -> L1 broadcast

        float w0 = w[0], w1 = w[1], w2 = w[2], w3 = w[3];
        float w4 = w[4], w5 = w[5], w6 = w[6], w7 = w[7];

        int idx = (b << 16) | (m << 9) | t4;   // float4 index into Ax

#pragma unroll
        for (int h = 0; h < 2; ++h) {
            // half h covers offsets h*QTR_ and h*QTR_ + 2*QTR_
            const float4* xh = xb + h * QTR_;

            // front-batch 16 loads (8 rows x 2 quarter-offsets) for MLP
            float4 a0 = __ldcs(&xh[0 * T4_]);  float4 b0 = __ldcs(&xh[0 * T4_ + 2 * QTR_]);
            float4 a1 = __ldcs(&xh[1 * T4_]);  float4 b1 = __ldcs(&xh[1 * T4_ + 2 * QTR_]);
            float4 a2 = __ldcs(&xh[2 * T4_]);  float4 b2 = __ldcs(&xh[2 * T4_ + 2 * QTR_]);
            float4 a3 = __ldcs(&xh[3 * T4_]);  float4 b3 = __ldcs(&xh[3 * T4_ + 2 * QTR_]);
            float4 a4 = __ldcs(&xh[4 * T4_]);  float4 b4 = __ldcs(&xh[4 * T4_ + 2 * QTR_]);
            float4 a5 = __ldcs(&xh[5 * T4_]);  float4 b5 = __ldcs(&xh[5 * T4_ + 2 * QTR_]);
            float4 a6 = __ldcs(&xh[6 * T4_]);  float4 b6 = __ldcs(&xh[6 * T4_ + 2 * QTR_]);
            float4 a7 = __ldcs(&xh[7 * T4_]);  float4 b7 = __ldcs(&xh[7 * T4_ + 2 * QTR_]);

            float4 accA, accB;
            accA.x = a0.x * w0; accA.y = a0.y * w0; accA.z = a0.z * w0; accA.w = a0.w * w0;
            accB.x = b0.x * w0; accB.y = b0.y * w0; accB.z = b0.z * w0; accB.w = b0.w * w0;

#define STEP(av, bv, wc) \
            accA.x = fmaf(av.x, wc, accA.x); accA.y = fmaf(av.y, wc, accA.y); \
            accA.z = fmaf(av.z, wc, accA.z); accA.w = fmaf(av.w, wc, accA.w); \
            accB.x = fmaf(bv.x, wc, accB.x); accB.y = fmaf(bv.y, wc, accB.y); \
            accB.z = fmaf(bv.z, wc, accB.z); accB.w = fmaf(bv.w, wc, accB.w);

            STEP(a1, b1, w1)
            STEP(a2, b2, w2)
            STEP(a3, b3, w3)
            STEP(a4, b4, w4)
            STEP(a5, b5, w5)
            STEP(a6, b6, w6)
            STEP(a7, b7, w7)
#undef STEP

            __stcs(&((float4*)out)[idx + h * QTR_], accA);
            __stcs(&((float4*)out)[idx + h * QTR_ + 2 * QTR_], accB);
        }
    } else {
        // ---- A_full: four float4 outputs ----
        int p = qid - AX_QUADS;               // 0..AF_QUADS-1
#pragma unroll
        for (int h = 0; h < 4; ++h) {
            int aidx = p + h * AF_QUADS;      // 0..AF_VEC-1
            int row  = aidx >> 8;             // 256 float4 per 1024-col row
            int col0 = (aidx & 255) * 4;

            float4 v;
            float* vp = &v.x;
#pragma unroll
            for (int j = 0; j < 4; ++j) {
                int col = col0 + j;
                vp[j] = ((col >> 3) == row) ? W[row * C_ + (col & 7)] : 0.0f;
            }
            __stcs(&((float4*)(out + AX_ELEMS))[aidx], v);
        }
    }
}

extern "C" void kernel_launch(void* const* d_in, const int* in_sizes, int n_in,
                              void* d_out, int out_size)
{
    const float* x = (const float*)d_in[0];
    const float* W = (const float*)d_in[1];
    float* out = (float*)d_out;

    fused_kernel<<<NBLOCKS, NTHREADS>>>(x, W, out);
}

// round 8
// speedup vs baseline: 1.0570x; 1.0570x over previous
#include <cuda_runtime.h>

// Ax[b,m,t] = sum_{c=0..7} x[b, m*8+c, t] * W[m,c]
// x: (16, 1024, 2048) f32, W: (128, 8) f32
// out: Ax (4194304 floats) then A_full (128*1024 floats).
// Each thread produces FOUR float4 outputs (t4, t4+128, t4+256, t4+384 of one
// (b,m) channel group), as two 16-load halves. Exact-cover grid = 1056 blocks
// = one full 8-resident wave on 148 SMs.

#define B_ 16
#define M_ 128
#define C_ 8
#define T_ 2048
#define T4_ (T_ / 4)                   // 512 float4 per channel row
#define QTR_ 128                       // quarter of a row in float4
#define AX_ELEMS (B_ * M_ * T_)        // 4194304
#define AX_VEC   (AX_ELEMS / 4)        // 1048576 float4
#define AX_QUADS (AX_VEC / 4)          // 262144
#define AF_ELEMS (M_ * 1024)           // 131072
#define AF_VEC   (AF_ELEMS / 4)        // 32768 float4
#define AF_QUADS (AF_VEC / 4)          // 8192
#define TOTAL_QUADS (AX_QUADS + AF_QUADS)  // 270336

#define NTHREADS 256
#define NBLOCKS (TOTAL_QUADS / NTHREADS)   // 1056, exact; <= 1184 -> one wave

__global__ void __launch_bounds__(NTHREADS)
fused_kernel(const float* __restrict__ x, const float* __restrict__ W,
             float* __restrict__ out)
{
    int qid = blockIdx.x * NTHREADS + threadIdx.x;

    if (qid < AX_QUADS) {
        // ---- Ax path: four float4 outputs of one (b,m) channel group ----
        int t4 = qid & (QTR_ - 1);         // 0..127
        int m  = (qid >> 7) & (M_ - 1);    // 0..127
        int b  = qid >> 14;                // 0..15

        const float4* xb = (const float4*)(x + ((size_t)(b * 1024 + m * C_) * T_)) + t4;
        const float*  w  = W + m * C_;     // uniform within warp -> L1 broadcast

        float w0 = w[0], w1 = w[1], w2 = w[2], w3 = w[3];
        float w4 = w[4], w5 = w[5], w6 = w[6], w7 = w[7];

        int idx = (b << 16) | (m << 9) | t4;   // float4 index into Ax

#pragma unroll
        for (int h = 0; h < 2; ++h) {
            // half h covers offsets h*QTR_ and h*QTR_ + 2*QTR_
            const float4* xh = xb + h * QTR_;

            // front-batch 16 loads (8 rows x 2 quarter-offsets) for MLP
            float4 a0 = __ldcs(&xh[0 * T4_]);  float4 b0 = __ldcs(&xh[0 * T4_ + 2 * QTR_]);
            float4 a1 = __ldcs(&xh[1 * T4_]);  float4 b1 = __ldcs(&xh[1 * T4_ + 2 * QTR_]);
            float4 a2 = __ldcs(&xh[2 * T4_]);  float4 b2 = __ldcs(&xh[2 * T4_ + 2 * QTR_]);
            float4 a3 = __ldcs(&xh[3 * T4_]);  float4 b3 = __ldcs(&xh[3 * T4_ + 2 * QTR_]);
            float4 a4 = __ldcs(&xh[4 * T4_]);  float4 b4 = __ldcs(&xh[4 * T4_ + 2 * QTR_]);
            float4 a5 = __ldcs(&xh[5 * T4_]);  float4 b5 = __ldcs(&xh[5 * T4_ + 2 * QTR_]);
            float4 a6 = __ldcs(&xh[6 * T4_]);  float4 b6 = __ldcs(&xh[6 * T4_ + 2 * QTR_]);
            float4 a7 = __ldcs(&xh[7 * T4_]);  float4 b7 = __ldcs(&xh[7 * T4_ + 2 * QTR_]);

            float4 accA, accB;
            accA.x = a0.x * w0; accA.y = a0.y * w0; accA.z = a0.z * w0; accA.w = a0.w * w0;
            accB.x = b0.x * w0; accB.y = b0.y * w0; accB.z = b0.z * w0; accB.w = b0.w * w0;

#define STEP(av, bv, wc) \
            accA.x = fmaf(av.x, wc, accA.x); accA.y = fmaf(av.y, wc, accA.y); \
            accA.z = fmaf(av.z, wc, accA.z); accA.w = fmaf(av.w, wc, accA.w); \
            accB.x = fmaf(bv.x, wc, accB.x); accB.y = fmaf(bv.y, wc, accB.y); \
            accB.z = fmaf(bv.z, wc, accB.z); accB.w = fmaf(bv.w, wc, accB.w);

            STEP(a1, b1, w1)
            STEP(a2, b2, w2)
            STEP(a3, b3, w3)
            STEP(a4, b4, w4)
            STEP(a5, b5, w5)
            STEP(a6, b6, w6)
            STEP(a7, b7, w7)
#undef STEP

            __stcs(&((float4*)out)[idx + h * QTR_], accA);
            __stcs(&((float4*)out)[idx + h * QTR_ + 2 * QTR_], accB);
        }
    } else {
        // ---- A_full: four float4 outputs ----
        int p = qid - AX_QUADS;               // 0..AF_QUADS-1
#pragma unroll
        for (int h = 0; h < 4; ++h) {
            int aidx = p + h * AF_QUADS;      // 0..AF_VEC-1
            int row  = aidx >> 8;             // 256 float4 per 1024-col row
            int col0 = (aidx & 255) * 4;

            float4 v;
            float* vp = &v.x;
#pragma unroll
            for (int j = 0; j < 4; ++j) {
                int col = col0 + j;
                vp[j] = ((col >> 3) == row) ? W[row * C_ + (col & 7)] : 0.0f;
            }
            __stcs(&((float4*)(out + AX_ELEMS))[aidx], v);
        }
    }
}

extern "C" void kernel_launch(void* const* d_in, const int* in_sizes, int n_in,
                              void* d_out, int out_size)
{
    const float* x = (const float*)d_in[0];
    const float* W = (const float*)d_in[1];
    float* out = (float*)d_out;

    fused_kernel<<<NBLOCKS, NTHREADS>>>(x, W, out);
}

// round 9
// speedup vs baseline: 1.1609x; 1.0983x over previous
#include <cuda_runtime.h>

// Ax[b,m,t] = sum_{c=0..7} x[b, m*8+c, t] * W[m,c]
// x: (16, 1024, 2048) f32, W: (128, 8) f32
// out: Ax (4194304 floats) then A_full (128*1024 floats).
// Each thread produces FOUR float4 outputs (t4, t4+128, t4+256, t4+384 of one
// (b,m) channel group), as two 16-load halves. Exact-cover grid = 1056 blocks
// = one full 8-resident wave on 148 SMs.

#define B_ 16
#define M_ 128
#define C_ 8
#define T_ 2048
#define T4_ (T_ / 4)                   // 512 float4 per channel row
#define QTR_ 128                       // quarter of a row in float4
#define AX_ELEMS (B_ * M_ * T_)        // 4194304
#define AX_VEC   (AX_ELEMS / 4)        // 1048576 float4
#define AX_QUADS (AX_VEC / 4)          // 262144
#define AF_ELEMS (M_ * 1024)           // 131072
#define AF_VEC   (AF_ELEMS / 4)        // 32768 float4
#define AF_QUADS (AF_VEC / 4)          // 8192
#define TOTAL_QUADS (AX_QUADS + AF_QUADS)  // 270336

#define NTHREADS 256
#define NBLOCKS (TOTAL_QUADS / NTHREADS)   // 1056, exact; <= 1184 -> one wave

__global__ void __launch_bounds__(NTHREADS)
fused_kernel(const float* __restrict__ x, const float* __restrict__ W,
             float* __restrict__ out)
{
    int qid = blockIdx.x * NTHREADS + threadIdx.x;

    if (qid < AX_QUADS) {
        // ---- Ax path: four float4 outputs of one (b,m) channel group ----
        int t4 = qid & (QTR_ - 1);         // 0..127
        int m  = (qid >> 7) & (M_ - 1);    // 0..127
        int b  = qid >> 14;                // 0..15

        const float4* xb = (const float4*)(x + ((size_t)(b * 1024 + m * C_) * T_)) + t4;
        const float*  w  = W + m * C_;     // uniform within warp -> L1 broadcast

        float w0 = w[0], w1 = w[1], w2 = w[2], w3 = w[3];
        float w4 = w[4], w5 = w[5], w6 = w[6], w7 = w[7];

        int idx = (b << 16) | (m << 9) | t4;   // float4 index into Ax

#pragma unroll
        for (int h = 0; h < 2; ++h) {
            // half h covers offsets h*QTR_ and h*QTR_ + 2*QTR_
            const float4* xh = xb + h * QTR_;

            // front-batch 16 loads (8 rows x 2 quarter-offsets) for MLP
            float4 a0 = __ldcs(&xh[0 * T4_]);  float4 b0 = __ldcs(&xh[0 * T4_ + 2 * QTR_]);
            float4 a1 = __ldcs(&xh[1 * T4_]);  float4 b1 = __ldcs(&xh[1 * T4_ + 2 * QTR_]);
            float4 a2 = __ldcs(&xh[2 * T4_]);  float4 b2 = __ldcs(&xh[2 * T4_ + 2 * QTR_]);
            float4 a3 = __ldcs(&xh[3 * T4_]);  float4 b3 = __ldcs(&xh[3 * T4_ + 2 * QTR_]);
            float4 a4 = __ldcs(&xh[4 * T4_]);  float4 b4 = __ldcs(&xh[4 * T4_ + 2 * QTR_]);
            float4 a5 = __ldcs(&xh[5 * T4_]);  float4 b5 = __ldcs(&xh[5 * T4_ + 2 * QTR_]);
            float4 a6 = __ldcs(&xh[6 * T4_]);  float4 b6 = __ldcs(&xh[6 * T4_ + 2 * QTR_]);
            float4 a7 = __ldcs(&xh[7 * T4_]);  float4 b7 = __ldcs(&xh[7 * T4_ + 2 * QTR_]);

            float4 accA, accB;
            accA.x = a0.x * w0; accA.y = a0.y * w0; accA.z = a0.z * w0; accA.w = a0.w * w0;
            accB.x = b0.x * w0; accB.y = b0.y * w0; accB.z = b0.z * w0; accB.w = b0.w * w0;

#define STEP(av, bv, wc) \
            accA.x = fmaf(av.x, wc, accA.x); accA.y = fmaf(av.y, wc, accA.y); \
            accA.z = fmaf(av.z, wc, accA.z); accA.w = fmaf(av.w, wc, accA.w); \
            accB.x = fmaf(bv.x, wc, accB.x); accB.y = fmaf(bv.y, wc, accB.y); \
            accB.z = fmaf(bv.z, wc, accB.z); accB.w = fmaf(bv.w, wc, accB.w);

            STEP(a1, b1, w1)
            STEP(a2, b2, w2)
            STEP(a3, b3, w3)
            STEP(a4, b4, w4)
            STEP(a5, b5, w5)
            STEP(a6, b6, w6)
            STEP(a7, b7, w7)
#undef STEP

            __stcs(&((float4*)out)[idx + h * QTR_], accA);
            __stcs(&((float4*)out)[idx + h * QTR_ + 2 * QTR_], accB);
        }
    } else {
        // ---- A_full: four float4 outputs ----
        int p = qid - AX_QUADS;               // 0..AF_QUADS-1
#pragma unroll
        for (int h = 0; h < 4; ++h) {
            int aidx = p + h * AF_QUADS;      // 0..AF_VEC-1
            int row  = aidx >> 8;             // 256 float4 per 1024-col row
            int col0 = (aidx & 255) * 4;

            float4 v;
            float* vp = &v.x;
#pragma unroll
            for (int j = 0; j < 4; ++j) {
                int col = col0 + j;
                vp[j] = ((col >> 3) == row) ? W[row * C_ + (col & 7)] : 0.0f;
            }
            __stcs(&((float4*)(out + AX_ELEMS))[aidx], v);
        }
    }
}

extern "C" void kernel_launch(void* const* d_in, const int* in_sizes, int n_in,
                              void* d_out, int out_size)
{
    const float* x = (const float*)d_in[0];
    const float* W = (const float*)d_in[1];
    float* out = (float*)d_out;

    fused_kernel<<<NBLOCKS, NTHREADS>>>(x, W, out);
}